// round 1
// baseline (speedup 1.0000x reference)
#include <cuda_runtime.h>
#include <cuda_bf16.h>
#include <cstdint>

// ---------------------------------------------------------------------------
// CapsuleNetwork forward:
//  conv 9x9 valid + relu -> xf[64][12800]
//  s1[b,j,m] = (1/8) * sum_k (sum_c W1[j,k,m,c]) * xf[b,k]   (routing(1) collapses)
//  v1 = squash(s1)
//  u2[b,j,k,m] = sum_c W2[j,k,m,c] * v1[b,k,c]
//  v2 = routing(u2, 3)  -> out [64,10,16]
// ---------------------------------------------------------------------------

#define B_SZ 64
#define CH 32
#define IN_UNITS 12800      // 32*20*20
#define KTILE 128
#define NKT 100             // 12800 / 128
#define KC 64               // chunk of k per phase

__device__ float g_xf[B_SZ * IN_UNITS];          // 3.28 MB  [b][k]
__device__ float g_part[NKT * B_SZ * 64];        // 1.64 MB  [ktile][b][j*8+m]

// ---------------------------------------------------------------------------
// Kernel 1: conv 9x9 valid + bias + relu, write xf[b][c*400 + y*20 + x]
// grid: 512 blocks = (b<<3)|cg, cg = group of 4 channels. block: 320 threads.
// thread = (c4, y, xg): computes 5 outputs along x with register sliding window
// ---------------------------------------------------------------------------
__global__ __launch_bounds__(320) void conv_kernel(
    const float* __restrict__ x, const float* __restrict__ w,
    const float* __restrict__ bias)
{
    int blk = blockIdx.x;
    int b = blk >> 3, cg = blk & 7;
    int t = threadIdx.x;

    __shared__ float xs[784];
    __shared__ float ws[4 * 81];

    for (int i = t; i < 784; i += 320) xs[i] = x[b * 784 + i];
    for (int i = t; i < 324; i += 320) ws[i] = w[cg * 324 + i];
    __syncthreads();

    int c4 = t / 80;
    int r  = t % 80;
    int y  = r >> 2;
    int x0 = (r & 3) * 5;

    float acc0 = 0.f, acc1 = 0.f, acc2 = 0.f, acc3 = 0.f, acc4 = 0.f;

    #pragma unroll
    for (int i = 0; i < 9; i++) {
        float wr[9];
        #pragma unroll
        for (int j = 0; j < 9; j++) wr[j] = ws[c4 * 81 + i * 9 + j];
        float xr[13];
        #pragma unroll
        for (int u = 0; u < 13; u++) xr[u] = xs[(y + i) * 28 + x0 + u];
        #pragma unroll
        for (int j = 0; j < 9; j++) {
            acc0 = fmaf(xr[0 + j], wr[j], acc0);
            acc1 = fmaf(xr[1 + j], wr[j], acc1);
            acc2 = fmaf(xr[2 + j], wr[j], acc2);
            acc3 = fmaf(xr[3 + j], wr[j], acc3);
            acc4 = fmaf(xr[4 + j], wr[j], acc4);
        }
    }

    int c = cg * 4 + c4;
    float bv = bias[c];
    int k0 = c * 400 + y * 20 + x0;
    float* dst = &g_xf[(size_t)b * IN_UNITS + k0];
    dst[0] = fmaxf(acc0 + bv, 0.f);
    dst[1] = fmaxf(acc1 + bv, 0.f);
    dst[2] = fmaxf(acc2 + bv, 0.f);
    dst[3] = fmaxf(acc3 + bv, 0.f);
    dst[4] = fmaxf(acc4 + bv, 0.f);
}

// ---------------------------------------------------------------------------
// Kernel 2: the W1 stream (HBM-bound, 105 MB).
// grid (NKT, 8j), block 512 threads.
// Per chunk of 64 k: phase1 streams W1[j, kchunk, :, :] as float4, reduces c
// via 8-lane shuffle groups into wsum_s[m][kk]; phase2: thread (b,m)
// accumulates sum_kk wsum[m][kk] * xf[b][kk], vectorized LDS.128.
// Deterministic partials to g_part (no atomics).
// ---------------------------------------------------------------------------
__global__ __launch_bounds__(512) void caps1_kernel(const float* __restrict__ W1)
{
    int kt = blockIdx.x;       // 0..99
    int j  = blockIdx.y;       // 0..7
    int t  = threadIdx.x;      // 0..511

    __shared__ float xf_s[B_SZ * 132];   // [b][kk], pad 132
    __shared__ float wsum_s[8 * 68];     // [m][kk], pad 68

    int kt0 = kt * KTILE;

    // load xf tile [64][128]
    #pragma unroll
    for (int i = 0; i < 16; i++) {
        int idx = t + 512 * i;
        int bb = idx >> 7, kk = idx & 127;
        xf_s[bb * 132 + kk] = g_xf[(size_t)bb * IN_UNITS + kt0 + kk];
    }

    int b = t >> 3, m = t & 7;
    float a0 = 0.f, a1 = 0.f, a2 = 0.f, a3 = 0.f;

    const float4* Wv = (const float4*)(W1) + (size_t)(j * IN_UNITS + kt0) * 64;

    #pragma unroll
    for (int ch = 0; ch < 2; ch++) {
        __syncthreads();   // protect wsum_s reuse + (first iter) xf_s fill
        // phase 1: reduce c (32) for 64 k's; chunk = 4096 float4
        #pragma unroll
        for (int i = 0; i < 8; i++) {
            float4 v = Wv[ch * 4096 + t + 512 * i];
            float p = (v.x + v.y) + (v.z + v.w);
            p += __shfl_xor_sync(0xffffffffu, p, 1);
            p += __shfl_xor_sync(0xffffffffu, p, 2);
            p += __shfl_xor_sync(0xffffffffu, p, 4);
            if ((t & 7) == 0) {
                int km = (t >> 3) + 64 * i;      // k_local*8 + m
                wsum_s[(km & 7) * 68 + (km >> 3)] = p;
            }
        }
        __syncthreads();
        // phase 2
        const float4* wr = (const float4*)&wsum_s[m * 68];
        const float4* xr = (const float4*)&xf_s[b * 132 + ch * 64];
        #pragma unroll
        for (int q = 0; q < 16; q++) {
            float4 w4 = wr[q];
            float4 x4 = xr[q];
            a0 = fmaf(w4.x, x4.x, a0);
            a1 = fmaf(w4.y, x4.y, a1);
            a2 = fmaf(w4.z, x4.z, a2);
            a3 = fmaf(w4.w, x4.w, a3);
        }
    }

    g_part[(size_t)kt * (B_SZ * 64) + b * 64 + j * 8 + m] = (a0 + a1) + (a2 + a3);
}

// ---------------------------------------------------------------------------
// Kernel 3: finalize s1 (fixed-order partial reduction), squash -> v1,
// u2 transform, routing(3), output. One block per batch, 160 threads=(j,m).
// ---------------------------------------------------------------------------
__global__ __launch_bounds__(160) void caps2_kernel(
    const float* __restrict__ W2, float* __restrict__ out)
{
    int b = blockIdx.x;
    int t = threadIdx.x;           // 0..159 = 5 full warps

    __shared__ float ss[64];       // s1[b][j][m]
    __shared__ float v1s[64];      // v1
    __shared__ float es[80];       // exp(bias logits)
    __shared__ float bs[80];       // routing logits b[j][k]
    __shared__ float ds[8];        // softmax denominators per k

    if (t < 64) {
        float s = 0.f;
        for (int kt = 0; kt < NKT; kt++)
            s += g_part[(size_t)kt * (B_SZ * 64) + b * 64 + t];
        ss[t] = s * 0.125f;
    }
    __syncthreads();
    if (t < 64) {
        int jj = t >> 3;
        float nsq = 0.f;
        #pragma unroll
        for (int mm = 0; mm < 8; mm++) { float v = ss[jj * 8 + mm]; nsq = fmaf(v, v, nsq); }
        float n = sqrtf(nsq);
        v1s[t] = ss[t] * (n / (1.f + nsq));
    }
    if (t < 80) bs[t] = 0.f;
    __syncthreads();

    int j = t >> 4, m = t & 15;    // j: 0..9, m: 0..15

    // u2[j][k][m] for k=0..7, in registers
    float u2r[8];
    const float4* W2v = (const float4*)W2;
    const float4* v1v = (const float4*)v1s;
    #pragma unroll
    for (int k = 0; k < 8; k++) {
        int base = ((j * 8 + k) * 16 + m) * 2;   // float4 index (8 c = 2 float4)
        float4 wa = W2v[base], wb = W2v[base + 1];
        float4 va = v1v[k * 2], vb = v1v[k * 2 + 1];
        u2r[k] = wa.x * va.x + wa.y * va.y + wa.z * va.z + wa.w * va.w
               + wb.x * vb.x + wb.y * vb.y + wb.z * vb.z + wb.w * vb.w;
    }

    float v = 0.f;
    for (int it = 0; it < 3; it++) {
        if (t < 80) es[t] = expf(bs[t]);
        __syncthreads();
        if (t < 8) {
            float d = 0.f;
            #pragma unroll
            for (int jj = 0; jj < 10; jj++) d += es[jj * 8 + t];
            ds[t] = d;
        }
        __syncthreads();
        float s = 0.f;
        #pragma unroll
        for (int k = 0; k < 8; k++)
            s = fmaf(es[j * 8 + k] / ds[k], u2r[k], s);
        float p = s * s;
        p += __shfl_xor_sync(0xffffffffu, p, 1);
        p += __shfl_xor_sync(0xffffffffu, p, 2);
        p += __shfl_xor_sync(0xffffffffu, p, 4);
        p += __shfl_xor_sync(0xffffffffu, p, 8);
        float n = sqrtf(p);
        v = s * (n / (1.f + p));
        __syncthreads();             // es reads done before bs update
        if (it < 2) {
            #pragma unroll
            for (int k = 0; k < 8; k++) {
                float q = u2r[k] * v;
                q += __shfl_xor_sync(0xffffffffu, q, 1);
                q += __shfl_xor_sync(0xffffffffu, q, 2);
                q += __shfl_xor_sync(0xffffffffu, q, 4);
                q += __shfl_xor_sync(0xffffffffu, q, 8);
                if (m == 0) bs[j * 8 + k] += q;
            }
        }
        __syncthreads();
    }

    out[b * 160 + t] = v;
}

// ---------------------------------------------------------------------------
extern "C" void kernel_launch(void* const* d_in, const int* in_sizes, int n_in,
                              void* d_out, int out_size)
{
    const float* x      = (const float*)d_in[0];  // [64,1,28,28]
    const float* conv_w = (const float*)d_in[1];  // [32,1,9,9]
    const float* conv_b = (const float*)d_in[2];  // [32]
    const float* W1     = (const float*)d_in[3];  // [8,12800,8,32]
    const float* W2     = (const float*)d_in[4];  // [10,8,16,8]
    float* out = (float*)d_out;                   // [64,10,16]

    conv_kernel<<<512, 320>>>(x, conv_w, conv_b);
    caps1_kernel<<<dim3(NKT, 8), 512>>>(W1);
    caps2_kernel<<<B_SZ, 160>>>(W2, out);
}

// round 3
// speedup vs baseline: 1.1992x; 1.1992x over previous
#include <cuda_runtime.h>
#include <cuda_bf16.h>
#include <cstdint>

// ---------------------------------------------------------------------------
// CapsuleNetwork forward:
//  conv 9x9 valid + relu -> xf[64][12800]
//  s1[b,j,m] = (1/8) * sum_k (sum_c W1[j,k,m,c]) * xf[b,k]   (routing(1) collapses)
//  v1 = squash(s1)
//  u2[b,j,k,m] = sum_c W2[j,k,m,c] * v1[b,k,c]
//  v2 = routing(u2, 3)  -> out [64,10,16]
// ---------------------------------------------------------------------------

#define B_SZ 64
#define IN_UNITS 12800      // 32*20*20
#define KT2 32              // k per caps1 block
#define NKT2 400            // 12800 / 32

__device__ float g_xf[B_SZ * IN_UNITS];            // 3.28 MB  [b][k]
__device__ float g_part[NKT2 * B_SZ * 64];         // 6.55 MB  [kt][b][jm]

// ---------------------------------------------------------------------------
// Kernel 1: conv 9x9 valid + bias + relu -> xf[b][c*400 + y*20 + x]
// grid 128 = (b, 16-channel half); 320 threads = (c in 16) x (y in 20);
// each thread computes a full row of 20 x-outputs via register sliding window.
// ---------------------------------------------------------------------------
__global__ __launch_bounds__(320) void conv_kernel(
    const float* __restrict__ x, const float* __restrict__ w,
    const float* __restrict__ bias)
{
    int blk = blockIdx.x;
    int b = blk >> 1, ch = blk & 1;
    int t = threadIdx.x;

    __shared__ float xs[784];
    __shared__ float wsm[16 * 81];

    for (int i = t; i < 784; i += 320) xs[i] = x[b * 784 + i];
    for (int i = t; i < 1296; i += 320) wsm[i] = w[ch * 1296 + i];
    __syncthreads();

    int c = t / 20, y = t % 20;

    float acc[20];
    #pragma unroll
    for (int o = 0; o < 20; o++) acc[o] = 0.f;

    for (int i = 0; i < 9; i++) {
        float wr[9];
        #pragma unroll
        for (int jj = 0; jj < 9; jj++) wr[jj] = wsm[c * 81 + i * 9 + jj];
        float xr[28];
        #pragma unroll
        for (int u = 0; u < 28; u++) xr[u] = xs[(y + i) * 28 + u];
        #pragma unroll
        for (int jj = 0; jj < 9; jj++)
            #pragma unroll
            for (int o = 0; o < 20; o++)
                acc[o] = fmaf(xr[o + jj], wr[jj], acc[o]);
    }

    int cg = ch * 16 + c;
    float bv = bias[cg];
    float4* dst = (float4*)&g_xf[(size_t)b * IN_UNITS + cg * 400 + y * 20];
    #pragma unroll
    for (int q = 0; q < 5; q++) {
        float4 r;
        r.x = fmaxf(acc[q * 4 + 0] + bv, 0.f);
        r.y = fmaxf(acc[q * 4 + 1] + bv, 0.f);
        r.z = fmaxf(acc[q * 4 + 2] + bv, 0.f);
        r.w = fmaxf(acc[q * 4 + 3] + bv, 0.f);
        dst[q] = r;
    }
}

// ---------------------------------------------------------------------------
// Kernel 2: W1 stream (HBM-bound, 105 MB), all 8 j per block.
// grid NKT2=400 (kt), 512 threads.
// Phase1: stream W1[j, kt*32..+32, :, :] as float4, reduce c via 8-lane
//         shuffles -> ws[kk][jm] smem; also load xf tile transposed.
// Phase2: thread = (bq in 16, jm2 in 32): per kk one LDS.128 (xf, 4 b,
//         warp-broadcast) + one LDS.64 (wsum, 2 jm) for 8 FMA.
// Writes deterministic partials g_part[kt][b][jm]; no atomics.
// ---------------------------------------------------------------------------
__global__ __launch_bounds__(512) void caps1_kernel(const float* __restrict__ W1)
{
    int kt = blockIdx.x;       // 0..399
    int t  = threadIdx.x;      // 0..511

    __shared__ float xsT[KT2 * 68];   // [kk][b], row stride 68
    __shared__ float ws[KT2 * 68];    // [kk][jm], row stride 68

    // load xf tile transposed: thread (b = t>>3, k4 = t&7) loads float4
    {
        int bb = t >> 3, k4 = t & 7;
        float4 xv = *(const float4*)&g_xf[(size_t)bb * IN_UNITS + kt * KT2 + k4 * 4];
        xsT[(k4 * 4 + 0) * 68 + bb] = xv.x;
        xsT[(k4 * 4 + 1) * 68 + bb] = xv.y;
        xsT[(k4 * 4 + 2) * 68 + bb] = xv.z;
        xsT[(k4 * 4 + 3) * 68 + bb] = xv.w;
    }

    // phase 1: W1 stream + c-reduction
    const float4* __restrict__ Wv = (const float4*)W1;
    int lanec = t & 7;
    #pragma unroll
    for (int j = 0; j < 8; j++) {
        size_t base = (size_t)j * 819200 + (size_t)kt * 2048;   // float4 units
        #pragma unroll
        for (int i = 0; i < 4; i++) {
            int idx = i * 512 + t;
            float4 v = Wv[base + idx];
            float p = (v.x + v.y) + (v.z + v.w);
            p += __shfl_xor_sync(0xffffffffu, p, 1);
            p += __shfl_xor_sync(0xffffffffu, p, 2);
            p += __shfl_xor_sync(0xffffffffu, p, 4);
            if (lanec == 0) {
                int r = idx >> 3;               // kk*8 + m
                ws[(r >> 3) * 68 + j * 8 + (r & 7)] = p;
            }
        }
    }
    __syncthreads();

    // phase 2: s1 partial GEMM [64b x 64jm] over this 32-k tile
    int bq  = t >> 5;     // 0..15 -> b = 4*bq..
    int jm2 = t & 31;     // 0..31 -> jm = 2*jm2..

    float a0 = 0.f, a1 = 0.f, a2 = 0.f, a3 = 0.f;
    float a4 = 0.f, a5 = 0.f, a6 = 0.f, a7 = 0.f;

    #pragma unroll
    for (int kk = 0; kk < KT2; kk++) {
        float4 xv = *(const float4*)&xsT[kk * 68 + bq * 4];
        float2 wv = *(const float2*)&ws[kk * 68 + jm2 * 2];
        a0 = fmaf(xv.x, wv.x, a0);
        a1 = fmaf(xv.y, wv.x, a1);
        a2 = fmaf(xv.z, wv.x, a2);
        a3 = fmaf(xv.w, wv.x, a3);
        a4 = fmaf(xv.x, wv.y, a4);
        a5 = fmaf(xv.y, wv.y, a5);
        a6 = fmaf(xv.z, wv.y, a6);
        a7 = fmaf(xv.w, wv.y, a7);
    }

    float* dst = &g_part[(size_t)kt * 4096];
    int col = jm2 * 2;
    dst[(bq * 4 + 0) * 64 + col]     = a0;
    dst[(bq * 4 + 1) * 64 + col]     = a1;
    dst[(bq * 4 + 2) * 64 + col]     = a2;
    dst[(bq * 4 + 3) * 64 + col]     = a3;
    dst[(bq * 4 + 0) * 64 + col + 1] = a4;
    dst[(bq * 4 + 1) * 64 + col + 1] = a5;
    dst[(bq * 4 + 2) * 64 + col + 1] = a6;
    dst[(bq * 4 + 3) * 64 + col + 1] = a7;
}

// ---------------------------------------------------------------------------
// Kernel 3: reduce 400 partials (fixed order, high MLP), squash -> v1,
// u2 transform, routing(3), output. One block per batch, 512 threads.
// ---------------------------------------------------------------------------
__global__ __launch_bounds__(512) void caps2_kernel(
    const float* __restrict__ W2, float* __restrict__ out)
{
    int b = blockIdx.x;
    int t = threadIdx.x;

    __shared__ float ps[8 * 64];   // slice partials
    __shared__ float ss[64];       // s1[b][j][m]
    __shared__ float v1s[64];      // v1
    __shared__ float es[80];       // exp(routing logits)
    __shared__ float bs[80];       // routing logits b[j][k]
    __shared__ float ds[8];        // softmax denominators per k

    // partial reduction: 64 jm x 8 slices of 50 (fully unrolled -> high MLP)
    {
        int jm = t & 63, s = t >> 6;
        const float* src = &g_part[(size_t)(s * 50) * 4096 + b * 64 + jm];
        float acc = 0.f;
        #pragma unroll
        for (int q = 0; q < 50; q++) acc += src[(size_t)q * 4096];
        ps[s * 64 + jm] = acc;
    }
    __syncthreads();
    if (t < 64) {
        float s = 0.f;
        #pragma unroll
        for (int i = 0; i < 8; i++) s += ps[i * 64 + t];
        ss[t] = s * 0.125f;
    }
    __syncthreads();
    if (t < 64) {
        int jj = t >> 3;
        float nsq = 0.f;
        #pragma unroll
        for (int mm = 0; mm < 8; mm++) { float v = ss[jj * 8 + mm]; nsq = fmaf(v, v, nsq); }
        float n = sqrtf(nsq);
        v1s[t] = ss[t] * (n / (1.f + nsq));
    }
    if (t < 80) bs[t] = 0.f;
    __syncthreads();

    bool act = (t < 160);
    int jraw = t >> 4;
    int j = (jraw < 10) ? jraw : 0;    // clamp for inactive threads (safe smem idx)
    int m = t & 15;

    // u2[j][k][m] for k=0..7, in registers
    float u2r[8];
    const float4* W2v = (const float4*)W2;
    const float4* v1v = (const float4*)v1s;
    #pragma unroll
    for (int k = 0; k < 8; k++) {
        int base = ((j * 8 + k) * 16 + m) * 2;   // float4 index (8 c = 2 float4)
        float4 wa = W2v[base], wb = W2v[base + 1];
        float4 va = v1v[k * 2], vb = v1v[k * 2 + 1];
        u2r[k] = wa.x * va.x + wa.y * va.y + wa.z * va.z + wa.w * va.w
               + wb.x * vb.x + wb.y * vb.y + wb.z * vb.z + wb.w * vb.w;
    }

    float v = 0.f;
    for (int it = 0; it < 3; it++) {
        if (t < 80) es[t] = expf(bs[t]);
        __syncthreads();
        if (t < 8) {
            float d = 0.f;
            #pragma unroll
            for (int jj = 0; jj < 10; jj++) d += es[jj * 8 + t];
            ds[t] = d;
        }
        __syncthreads();
        float s = 0.f;
        #pragma unroll
        for (int k = 0; k < 8; k++)
            s = fmaf(es[j * 8 + k] / ds[k], u2r[k], s);
        float p = s * s;
        p += __shfl_xor_sync(0xffffffffu, p, 1);
        p += __shfl_xor_sync(0xffffffffu, p, 2);
        p += __shfl_xor_sync(0xffffffffu, p, 4);
        p += __shfl_xor_sync(0xffffffffu, p, 8);
        float n = sqrtf(p);
        v = s * (n / (1.f + p));
        __syncthreads();             // es reads done before bs update
        if (it < 2) {
            #pragma unroll
            for (int k = 0; k < 8; k++) {
                float q = u2r[k] * v;
                q += __shfl_xor_sync(0xffffffffu, q, 1);
                q += __shfl_xor_sync(0xffffffffu, q, 2);
                q += __shfl_xor_sync(0xffffffffu, q, 4);
                q += __shfl_xor_sync(0xffffffffu, q, 8);
                if (act && m == 0) bs[j * 8 + k] += q;
            }
        }
        __syncthreads();
    }

    if (act) out[b * 160 + t] = v;
}

// ---------------------------------------------------------------------------
extern "C" void kernel_launch(void* const* d_in, const int* in_sizes, int n_in,
                              void* d_out, int out_size)
{
    const float* x      = (const float*)d_in[0];  // [64,1,28,28]
    const float* conv_w = (const float*)d_in[1];  // [32,1,9,9]
    const float* conv_b = (const float*)d_in[2];  // [32]
    const float* W1     = (const float*)d_in[3];  // [8,12800,8,32]
    const float* W2     = (const float*)d_in[4];  // [10,8,16,8]
    float* out = (float*)d_out;                   // [64,10,16]

    conv_kernel<<<128, 320>>>(x, conv_w, conv_b);
    caps1_kernel<<<NKT2, 512>>>(W1);
    caps2_kernel<<<B_SZ, 512>>>(W2, out);
}